// round 17
// baseline (speedup 1.0000x reference)
#include <cuda_runtime.h>
#include <cuda_bf16.h>
#include <cstdint>

// Problem shape (fixed): B=32, Q=512, K=512, D=1024, fp32.
// Inputs: queries f32[B,Q,D], keys f32[B,K,D], temperature f32[], bias f32[]
// Output: attn f32[B,Q,K] then confidence f32[B,Q].
//
// Single fused kernel. GEMM: error-free bf16 2-term split, 3 MMA products on
// mma.sync m16n8k16 (at the measured ~16 cyc/SMSP issue floor). Softmax is
// fused via a per-row-group completion counter: the last of the 4 N-tile CTAs
// of each 128-row group runs the row softmax + confidence, overlapping with
// the remaining GEMM tiles' MMA work.

#define BATCH 32
#define QDIM 512
#define KDIM 512
#define DDIM 1024

#define TM 128
#define TN 128
#define NCHUNK 64                 // 64 chunks of k=16 floats

// Dynamic smem: 6 slots per operand tensor (4KB each slot)
#define SM_AH 0
#define SM_AL 24576
#define SM_BH 49152
#define SM_BL 73728
#define SM_MASK 98304
#define SMEM_TOTAL (98304 + 512)

// Completion counters, one per (batch, mtile) row group. Zero-initialized at
// module load; the finishing CTA resets its counter to 0, so every graph
// replay starts from a clean state. No device allocation.
__device__ int g_row_done[BATCH * (QDIM / TM)];

// ---------------- PTX helpers ----------------
__device__ __forceinline__ uint32_t smem_u32(const void* p) {
    uint32_t a;
    asm("{ .reg .u64 t; cvta.to.shared.u64 t, %1; cvt.u32.u64 %0, t; }"
        : "=r"(a) : "l"(p));
    return a;
}

#define LDSM4(r0, r1, r2, r3, addr)                                        \
    asm volatile("ldmatrix.sync.aligned.m8n8.x4.shared.b16 "               \
                 "{%0, %1, %2, %3}, [%4];"                                 \
                 : "=r"(r0), "=r"(r1), "=r"(r2), "=r"(r3) : "r"(addr))

#define STS128(addr, r0, r1, r2, r3)                                       \
    asm volatile("st.shared.v4.b32 [%0], {%1, %2, %3, %4};"                \
                 :: "r"(addr), "r"(r0), "r"(r1), "r"(r2), "r"(r3) : "memory")

#define MMA16816(c, a0, a1, a2, a3, b0, b1)                                \
    asm volatile("mma.sync.aligned.m16n8k16.row.col.f32.bf16.bf16.f32 "    \
                 "{%0, %1, %2, %3}, {%4, %5, %6, %7}, {%8, %9}, "          \
                 "{%0, %1, %2, %3};"                                       \
                 : "+f"((c)[0]), "+f"((c)[1]), "+f"((c)[2]), "+f"((c)[3])  \
                 : "r"(a0), "r"(a1), "r"(a2), "r"(a3), "r"(b0), "r"(b1))

__device__ __forceinline__ void split2(float x, float y,
                                       uint32_t& h, uint32_t& l) {
    __nv_bfloat162 hh = __floats2bfloat162_rn(x, y);
    float rx = x - __bfloat162float(hh.x);
    float ry = y - __bfloat162float(hh.y);
    __nv_bfloat162 ll = __floats2bfloat162_rn(rx, ry);
    h = reinterpret_cast<uint32_t&>(hh);
    l = reinterpret_cast<uint32_t&>(ll);
}

// Swizzled byte offset: row r (0..127), 16-byte chunk c (0..1); 32B rows.
__device__ __forceinline__ uint32_t swz(int r, int c) {
    return (uint32_t)(r * 32 + ((c ^ ((r >> 2) & 1)) << 4));
}

__device__ __forceinline__ float ex2f(float x) {
    float r;
    asm("ex2.approx.ftz.f32 %0, %1;" : "=f"(r) : "f"(x));
    return r;
}

// ---------------------------------------------------------------------------
// Fused kernel: GEMM tile + (for the last CTA of each row group) softmax.
// ---------------------------------------------------------------------------
__global__ __launch_bounds__(256, 2)
void fused_attn_kernel(const float* __restrict__ Qg,
                       const float* __restrict__ Kg,
                       const float* __restrict__ tptr,
                       const float* __restrict__ bptr,
                       float* __restrict__ out) {
    extern __shared__ __align__(128) uint8_t smem[];
    const uint32_t sb = smem_u32(smem);
    float* maskv = (float*)(smem + SM_MASK);
    __shared__ int s_last;

    const int tid  = threadIdx.x;
    const int lane = tid & 31;
    const int wid  = tid >> 5;
    const int wm   = wid & 3;          // 0..3  (M)
    const int wn   = wid >> 2;         // 0..1  (N)

    const int bn = blockIdx.x * TN;
    const int bm = blockIdx.y * TM;
    const int b  = blockIdx.z;

    const float* A  = Qg + (size_t)b * QDIM * DDIM;
    const float* Bp = Kg + (size_t)b * KDIM * DDIM;
    float*       C  = out + (size_t)b * QDIM * KDIM;

    if (tid < TN)
        maskv[tid] = (Bp[(size_t)(bn + tid) * DDIM] == 0.0f) ? 1.0f : 0.0f;

    const int pr = tid >> 1;           // 0..127
    const int ph = tid & 1;
    const uint32_t so = swz(pr, ph);
    const uint32_t stAh = sb + SM_AH + so;
    const uint32_t stAl = sb + SM_AL + so;
    const uint32_t stBh = sb + SM_BH + so;
    const uint32_t stBl = sb + SM_BL + so;
    const float* gA = A  + (size_t)(bm + pr) * DDIM + ph * 8;
    const float* gB = Bp + (size_t)(bn + pr) * DDIM + ph * 8;

    uint32_t lmA, lmB;
    {
        int r = wm * 32 + (lane & 15);
        int c = lane >> 4;
        lmA = swz(r, c);
    }
    {
        int r = wn * 64 + (lane & 7) + ((lane >> 4) << 3);
        int c = (lane >> 3) & 1;
        lmB = swz(r, c);
    }
    const uint32_t aAh = sb + SM_AH + lmA;
    const uint32_t aAl = sb + SM_AL + lmA;
    const uint32_t aBh = sb + SM_BH + lmB;
    const uint32_t aBl = sb + SM_BL + lmB;

    float acc[2][8][4];
    #pragma unroll
    for (int i = 0; i < 2; ++i)
        #pragma unroll
        for (int j = 0; j < 8; ++j)
            #pragma unroll
            for (int k = 0; k < 4; ++k) acc[i][j][k] = 0.0f;

    float4 va0, va1, vb0, vb1;         // the single held prefetch set

    #define LDG_CHUNK(c) do {                                              \
        const float* _pa = gA + (c) * 16;                                  \
        const float* _pb = gB + (c) * 16;                                  \
        va0 = *(const float4*)_pa;  va1 = *(const float4*)(_pa + 4);       \
        vb0 = *(const float4*)_pb;  vb1 = *(const float4*)(_pb + 4);       \
    } while (0)

    #define STS_CHUNK(q) do {                                              \
        const uint32_t _o = (uint32_t)(q) * 4096u;                         \
        uint32_t h0, h1, h2, h3, l0, l1, l2, l3;                           \
        split2(va0.x, va0.y, h0, l0); split2(va0.z, va0.w, h1, l1);        \
        split2(va1.x, va1.y, h2, l2); split2(va1.z, va1.w, h3, l3);        \
        STS128(stAh + _o, h0, h1, h2, h3);                                 \
        STS128(stAl + _o, l0, l1, l2, l3);                                 \
        split2(vb0.x, vb0.y, h0, l0); split2(vb0.z, vb0.w, h1, l1);        \
        split2(vb1.x, vb1.y, h2, l2); split2(vb1.z, vb1.w, h3, l3);        \
        STS128(stBh + _o, h0, h1, h2, h3);                                 \
        STS128(stBl + _o, l0, l1, l2, l3);                                 \
    } while (0)

    #define MMA_SLOT(q) do {                                               \
        const uint32_t _o = (uint32_t)(q) * 4096u;                         \
        uint32_t Ah[2][4], Al[2][4];                                       \
        LDSM4(Ah[0][0], Ah[0][1], Ah[0][2], Ah[0][3], aAh + _o);           \
        LDSM4(Ah[1][0], Ah[1][1], Ah[1][2], Ah[1][3], aAh + _o + 512);     \
        LDSM4(Al[0][0], Al[0][1], Al[0][2], Al[0][3], aAl + _o);           \
        LDSM4(Al[1][0], Al[1][1], Al[1][2], Al[1][3], aAl + _o + 512);     \
        _Pragma("unroll")                                                  \
        for (int q4 = 0; q4 < 4; ++q4) {                                   \
            uint32_t Bh[4], Bl[4];                                         \
            LDSM4(Bh[0], Bh[1], Bh[2], Bh[3], aBh + _o + q4 * 512);        \
            LDSM4(Bl[0], Bl[1], Bl[2], Bl[3], aBl + _o + q4 * 512);        \
            _Pragma("unroll")                                              \
            for (int mi = 0; mi < 2; ++mi) {                               \
                float* c0 = acc[mi][2 * q4];                               \
                float* c1 = acc[mi][2 * q4 + 1];                           \
                MMA16816(c0, Ah[mi][0], Ah[mi][1], Ah[mi][2], Ah[mi][3], Bh[0], Bh[1]); \
                MMA16816(c0, Ah[mi][0], Ah[mi][1], Ah[mi][2], Ah[mi][3], Bl[0], Bl[1]); \
                MMA16816(c0, Al[mi][0], Al[mi][1], Al[mi][2], Al[mi][3], Bh[0], Bh[1]); \
                MMA16816(c1, Ah[mi][0], Ah[mi][1], Ah[mi][2], Ah[mi][3], Bh[2], Bh[3]); \
                MMA16816(c1, Ah[mi][0], Ah[mi][1], Ah[mi][2], Ah[mi][3], Bl[2], Bl[3]); \
                MMA16816(c1, Al[mi][0], Al[mi][1], Al[mi][2], Al[mi][3], Bh[2], Bh[3]); \
            }                                                              \
        }                                                                  \
    } while (0)

    LDG_CHUNK(0); STS_CHUNK(0);
    LDG_CHUNK(1); STS_CHUNK(1);
    LDG_CHUNK(2); STS_CHUNK(2);
    LDG_CHUNK(3);
    __syncthreads();

    #pragma unroll 1
    for (int i = 0; i < 10; ++i) {
        STS_CHUNK(3); LDG_CHUNK(6 * i + 4);
        MMA_SLOT(0);
        STS_CHUNK(4); LDG_CHUNK(6 * i + 5);
        MMA_SLOT(1);
        STS_CHUNK(5); LDG_CHUNK(6 * i + 6);
        MMA_SLOT(2);
        __syncthreads();
        STS_CHUNK(0); LDG_CHUNK(6 * i + 7);
        MMA_SLOT(3);
        STS_CHUNK(1); LDG_CHUNK(6 * i + 8);
        MMA_SLOT(4);
        STS_CHUNK(2); LDG_CHUNK(6 * i + 9);
        MMA_SLOT(5);
        __syncthreads();
    }
    STS_CHUNK(3);                       // chunk 63 -> slot 3
    MMA_SLOT(0);
    MMA_SLOT(1);
    MMA_SLOT(2);
    __syncthreads();
    MMA_SLOT(3);                        // chunk 63

    // ---- GEMM epilogue: apply key mask, write logits ----
    const float NEG_INF = __int_as_float(0xff800000);
    const int mrow = bm + wm * 32 + (lane >> 2);
    const int ncl  = wn * 64 + (lane & 3) * 2;
    #pragma unroll
    for (int mi = 0; mi < 2; ++mi) {
        #pragma unroll
        for (int ni = 0; ni < 8; ++ni) {
            const int nc = ncl + ni * 8;
            const float m0 = maskv[nc];
            const float m1 = maskv[nc + 1];
            const float* c = acc[mi][ni];
            float2 v0, v1;
            v0.x = (m0 != 0.0f) ? NEG_INF : c[0];
            v0.y = (m1 != 0.0f) ? NEG_INF : c[1];
            v1.x = (m0 != 0.0f) ? NEG_INF : c[2];
            v1.y = (m1 != 0.0f) ? NEG_INF : c[3];
            float* base = C + (size_t)(mrow + mi * 16) * KDIM + bn + nc;
            *(float2*)base              = v0;
            *(float2*)(base + 8 * KDIM) = v1;
        }
    }
    #undef LDG_CHUNK
    #undef STS_CHUNK
    #undef MMA_SLOT

    // ---- row-group completion: last of 4 N-tile CTAs runs the softmax ----
    __threadfence();                          // release our logit stores
    if (tid == 0) {
        const int ci = b * (QDIM / TM) + blockIdx.y;
        const int old = atomicAdd(&g_row_done[ci], 1);
        s_last = (old == 3) ? (ci + 1) : 0;   // nonzero flag carries index+1
    }
    __syncthreads();
    if (s_last == 0) return;
    __threadfence();                          // acquire peers' logit stores

    // ---- fused softmax + confidence for rows [bm, bm+TM) of batch b ----
    const float L2E = 1.4426950408889634f;
    const float bias = bptr[0];
    const float temp = tptr[0];
    #pragma unroll 1
    for (int r = wid; r < TM; r += 8) {
        float* lr = C + (size_t)(bm + r) * KDIM;

        float4 v0 = *(const float4*)(lr + lane * 4);
        float4 v1 = *(const float4*)(lr + 128 + lane * 4);
        float4 v2 = *(const float4*)(lr + 256 + lane * 4);
        float4 v3 = *(const float4*)(lr + 384 + lane * 4);

        float m0 = fmaxf(fmaxf(v0.x, v0.y), fmaxf(v0.z, v0.w));
        float m1 = fmaxf(fmaxf(v1.x, v1.y), fmaxf(v1.z, v1.w));
        float m2 = fmaxf(fmaxf(v2.x, v2.y), fmaxf(v2.z, v2.w));
        float m3 = fmaxf(fmaxf(v3.x, v3.y), fmaxf(v3.z, v3.w));
        float m = fmaxf(fmaxf(m0, m1), fmaxf(m2, m3));
        #pragma unroll
        for (int o = 16; o > 0; o >>= 1)
            m = fmaxf(m, __shfl_xor_sync(0xffffffffu, m, o));

        const float nm = -m * L2E;
        float e[16];
        e[0]  = ex2f(fmaf(v0.x, L2E, nm)); e[1]  = ex2f(fmaf(v0.y, L2E, nm));
        e[2]  = ex2f(fmaf(v0.z, L2E, nm)); e[3]  = ex2f(fmaf(v0.w, L2E, nm));
        e[4]  = ex2f(fmaf(v1.x, L2E, nm)); e[5]  = ex2f(fmaf(v1.y, L2E, nm));
        e[6]  = ex2f(fmaf(v1.z, L2E, nm)); e[7]  = ex2f(fmaf(v1.w, L2E, nm));
        e[8]  = ex2f(fmaf(v2.x, L2E, nm)); e[9]  = ex2f(fmaf(v2.y, L2E, nm));
        e[10] = ex2f(fmaf(v2.z, L2E, nm)); e[11] = ex2f(fmaf(v2.w, L2E, nm));
        e[12] = ex2f(fmaf(v3.x, L2E, nm)); e[13] = ex2f(fmaf(v3.y, L2E, nm));
        e[14] = ex2f(fmaf(v3.z, L2E, nm)); e[15] = ex2f(fmaf(v3.w, L2E, nm));

        float t0 = (e[0] + e[1])   + (e[2] + e[3]);
        float t1 = (e[4] + e[5])   + (e[6] + e[7]);
        float t2 = (e[8] + e[9])   + (e[10] + e[11]);
        float t3 = (e[12] + e[13]) + (e[14] + e[15]);
        float s = (t0 + t1) + (t2 + t3);
        #pragma unroll
        for (int o = 16; o > 0; o >>= 1)
            s += __shfl_xor_sync(0xffffffffu, s, o);

        const float inv = 1.0f / s;
        *(float4*)(lr + lane * 4)       = make_float4(e[0]*inv,  e[1]*inv,  e[2]*inv,  e[3]*inv);
        *(float4*)(lr + 128 + lane * 4) = make_float4(e[4]*inv,  e[5]*inv,  e[6]*inv,  e[7]*inv);
        *(float4*)(lr + 256 + lane * 4) = make_float4(e[8]*inv,  e[9]*inv,  e[10]*inv, e[11]*inv);
        *(float4*)(lr + 384 + lane * 4) = make_float4(e[12]*inv, e[13]*inv, e[14]*inv, e[15]*inv);

        if (lane == 0) {
            const float lse = m + logf(s);
            const float x = (lse + bias) * temp;
            out[(size_t)BATCH * QDIM * KDIM + b * QDIM + bm + r] =
                1.0f / (1.0f + __expf(-x));
        }
    }

    // reset the counter for the next (graph-replayed) launch
    __syncthreads();
    if (tid == 0) g_row_done[s_last - 1] = 0;
}

// ---------------------------------------------------------------------------
extern "C" void kernel_launch(void* const* d_in, const int* in_sizes, int n_in,
                              void* d_out, int out_size) {
    const float* q    = (const float*)d_in[0];
    const float* k    = (const float*)d_in[1];
    const float* temp = (const float*)d_in[2];
    const float* bias = (const float*)d_in[3];
    float* out = (float*)d_out;

    cudaFuncSetAttribute(fused_attn_kernel,
                         cudaFuncAttributeMaxDynamicSharedMemorySize, SMEM_TOTAL);

    dim3 ggrid(KDIM / TN, QDIM / TM, BATCH);   // (4, 4, 32) = 512 CTAs
    fused_attn_kernel<<<ggrid, 256, SMEM_TOTAL>>>(q, k, temp, bias, out);
}